// round 16
// baseline (speedup 1.0000x reference)
#include <cuda_runtime.h>
#include <cuda_bf16.h>
#include <math.h>
#include <stdint.h>

#define C_CH   128
#define N_PTS  32768
#define K_PWL  20
#define LATENT 8
#define HID    8
#define NSEG   (K_PWL - 1)

// ---------------- scratch (static device memory; no allocations) ----------------
// x/e stored as int16 fixed-point: q = round(v * 32767), |v| <= 1 (tanh output).
__device__ short g_xq[(size_t)C_CH * N_PTS];
__device__ short g_eq[(size_t)C_CH * N_PTS];
__device__ float g_slope[C_CH * NSEG];
__device__ float g_icept[C_CH * NSEG];

// Statically initialized; re-armed for the next replay by out_kernel (runs
// strictly after pass_e's finalize consumed them). Every launch leaves the
// same state -> deterministic across correctness run / capture / replays.
#define I8(v) v, v, v, v, v, v, v, v
#define I64(v) I8(v), I8(v), I8(v), I8(v), I8(v), I8(v), I8(v), I8(v)
__device__ int g_min_q[C_CH] = { I64(0x7FFFFFFF), I64(0x7FFFFFFF) };
__device__ int g_max_q[C_CH] = { I64(-0x7FFFFFFF - 1), I64(-0x7FFFFFFF - 1) };

__device__ float g_minv[C_CH];
__device__ float g_scale[C_CH];
__device__ float g_psum[2048];
__device__ float g_psumsq[2048];
__device__ float g_eA;   // 0.1 * invstd * (1/32767)
__device__ float g_eB;   // -0.1 * mean * invstd
__device__ unsigned int g_done;  // zero-init; self-resets each run

#define QSCALE 32767.0f
#define QINV   (1.0f / 32767.0f)

// xp = linspace(0,1,20) in f32
#define XPV(k) ((float)((double)(k) / 19.0))
__constant__ float c_xp[K_PWL] = {
    XPV(0), XPV(1), XPV(2), XPV(3), XPV(4), XPV(5), XPV(6), XPV(7), XPV(8), XPV(9),
    XPV(10), XPV(11), XPV(12), XPV(13), XPV(14), XPV(15), XPV(16), XPV(17), XPV(18), XPV(19)
};

// ---------------- helpers ----------------
// Clamped fast tanh (gen path only; off the hot loop).
__device__ __forceinline__ float tanh_fast(float x) {
    x = fminf(fmaxf(x, -30.0f), 30.0f);
    float t = __expf(2.0f * x);
    return __fdividef(t - 1.0f, t + 1.0f);
}

// Lean 5-instruction tanh (validated rounds 13-15).
__device__ __forceinline__ float tanh5(float x) {
    float t;
    asm("ex2.approx.f32 %0, %1;" : "=f"(t) : "f"(x * 2.8853900817779268f));
    float r;
    asm("rcp.approx.f32 %0, %1;" : "=f"(r) : "f"(t + 1.0f));
    return fmaf(t, r, -r);
}

// ---------------- gen path: PWL generator, runs inside pass_e's finalize block ----------------
// Block-uniform path (whole block enters), threads 0..127 active for gen math,
// all 256 participate in the __syncthreads.
__device__ void gen_pwl_inline(int tid,
                               const float* __restrict__ zf,
                               const float* __restrict__ Wf1, const float* __restrict__ bf1,
                               const float* __restrict__ Wf2, const float* __restrict__ bf2,
                               const void* __restrict__ dirs_raw,
                               unsigned int* flags_sh) {
    const int c = tid;
    if (tid == 0) *flags_sh = 0u;
    __syncthreads();
    if (c < C_CH) {
        unsigned char v = ((const unsigned char*)dirs_raw)[c];
        unsigned int f = 0u;
        if ((c & 3) != 0 && v != 0) f |= 1u;
        if (v > 1) f |= 2u;
        if (f) atomicOr(flags_sh, f);
    }
    __syncthreads();
    if (c >= C_CH) return;
    const unsigned int flags = *flags_sh;
    // mode: 0 = int32, 1 = uint8/bool, 2 = float32
    const int mode = (!(flags & 1u)) ? 0 : ((!(flags & 2u)) ? 1 : 2);

    float z[LATENT];
#pragma unroll
    for (int i = 0; i < LATENT; i++) z[i] = zf[c * LATENT + i];

    float h[HID];
#pragma unroll
    for (int j = 0; j < HID; j++) h[j] = bf1[j];
#pragma unroll
    for (int i = 0; i < LATENT; i++)
#pragma unroll
        for (int j = 0; j < HID; j++) h[j] = fmaf(z[i], Wf1[i * HID + j], h[j]);
#pragma unroll
    for (int j = 0; j < HID; j++) h[j] = tanh_fast(h[j]);

    float pts[K_PWL];
#pragma unroll
    for (int k = 0; k < K_PWL; k++) {
        float s = bf2[k];
#pragma unroll
        for (int j = 0; j < HID; j++) s = fmaf(h[j], Wf2[j * K_PWL + k], s);
        pts[k] = tanh_fast(s);
    }
    // insertion sort ascending
    for (int a = 1; a < K_PWL; a++) {
        float v = pts[a];
        int b = a - 1;
        while (b >= 0 && pts[b] > v) { pts[b + 1] = pts[b]; b--; }
        pts[b + 1] = v;
    }
    bool dir;
    if (mode == 0)      dir = ((const int*)dirs_raw)[c] != 0;
    else if (mode == 1) dir = ((const unsigned char*)dirs_raw)[c] != 0;
    else                dir = ((const float*)dirs_raw)[c] > 0.5f;

    // Per-segment slope/intercept: y(xv) = sl*xv + ic on [xp[k], xp[k+1]]
    for (int k = 0; k < NSEG; k++) {
        float y0 = dir ? pts[k]     : pts[K_PWL - 1 - k];
        float y1 = dir ? pts[k + 1] : pts[K_PWL - 2 - k];
        float sl = (y1 - y0) / (c_xp[k + 1] - c_xp[k] + 1e-7f);
        g_slope[c * NSEG + k] = sl;
        g_icept[c * NSEG + k] = fmaf(-c_xp[k], sl, y0);
    }
}

// ---------------- K1: x MLP + per-channel min/max (int16 scratch) ----------------
__global__ void __launch_bounds__(256) pass_x_kernel(
    const float* __restrict__ zx,
    const float* __restrict__ W1, const float* __restrict__ b1,
    const float* __restrict__ W2, const float* __restrict__ b2) {
    float W1r[64];
#pragma unroll
    for (int i = 0; i < 64; i++) W1r[i] = __ldg(W1 + i);
    float b1r[HID], W2r[HID];
#pragma unroll
    for (int j = 0; j < HID; j++) { b1r[j] = __ldg(b1 + j); W2r[j] = __ldg(W2 + j); }
    float b2r = __ldg(b2);

    const int c = blockIdx.y;
    const int tid = threadIdx.x;
    const size_t base = (size_t)c * N_PTS;
    const int n0 = blockIdx.x * 2048;

    int lmin = 0x7FFFFFFF, lmax = (int)0x80000000;
#pragma unroll
    for (int k = 0; k < 8; k++) {
        int n = n0 + k * 256 + tid;
        const float4* p = reinterpret_cast<const float4*>(zx + (base + n) * LATENT);
        float4 a = p[0], bq = p[1];
        float z[8] = {a.x, a.y, a.z, a.w, bq.x, bq.y, bq.z, bq.w};
        float h[HID];
#pragma unroll
        for (int j = 0; j < HID; j++) h[j] = b1r[j];
#pragma unroll
        for (int i = 0; i < LATENT; i++)
#pragma unroll
            for (int j = 0; j < HID; j++) h[j] = fmaf(z[i], W1r[i * HID + j], h[j]);
        float o = b2r;
#pragma unroll
        for (int j = 0; j < HID; j++) o = fmaf(tanh5(h[j]), W2r[j], o);
        float xv = tanh5(o);
        int q = __float2int_rn(xv * QSCALE);
        g_xq[base + n] = (short)q;
        lmin = min(lmin, q);
        lmax = max(lmax, q);
    }

    __shared__ int red1[256];
    __shared__ int red2[256];
    red1[tid] = lmin; red2[tid] = lmax; __syncthreads();
    for (int s = 128; s; s >>= 1) {
        if (tid < s) {
            red1[tid] = min(red1[tid], red1[tid + s]);
            red2[tid] = max(red2[tid], red2[tid + s]);
        }
        __syncthreads();
    }
    if (tid == 0) {
        atomicMin(&g_min_q[c], red1[0]);
        atomicMax(&g_max_q[c], red2[0]);
    }
}

// ---------------- K2: e MLP + partials + last-block finalize + PWL gen ----------------
__global__ void __launch_bounds__(256) pass_e_kernel(
    const float* __restrict__ ze,
    const float* __restrict__ W1, const float* __restrict__ b1,
    const float* __restrict__ W2, const float* __restrict__ b2,
    const float* __restrict__ zf,
    const float* __restrict__ Wf1, const float* __restrict__ bf1,
    const float* __restrict__ Wf2, const float* __restrict__ bf2,
    const void* __restrict__ dirs_raw) {
    float W1r[64];
#pragma unroll
    for (int i = 0; i < 64; i++) W1r[i] = __ldg(W1 + i);
    float b1r[HID], W2r[HID];
#pragma unroll
    for (int j = 0; j < HID; j++) { b1r[j] = __ldg(b1 + j); W2r[j] = __ldg(W2 + j); }
    float b2r = __ldg(b2);

    const int c = blockIdx.y;
    const int tid = threadIdx.x;
    const size_t base = (size_t)c * N_PTS;
    const int n0 = blockIdx.x * 2048;

    float ls = 0.0f, lq = 0.0f;
#pragma unroll
    for (int k = 0; k < 8; k++) {
        int n = n0 + k * 256 + tid;
        const float4* p = reinterpret_cast<const float4*>(ze + (base + n) * LATENT);
        float4 a = p[0], bq = p[1];
        float z[8] = {a.x, a.y, a.z, a.w, bq.x, bq.y, bq.z, bq.w};
        float h[HID];
#pragma unroll
        for (int j = 0; j < HID; j++) h[j] = b1r[j];
#pragma unroll
        for (int i = 0; i < LATENT; i++)
#pragma unroll
            for (int j = 0; j < HID; j++) h[j] = fmaf(z[i], W1r[i * HID + j], h[j]);
        float o = b2r;
#pragma unroll
        for (int j = 0; j < HID; j++) o = fmaf(tanh5(h[j]), W2r[j], o);
        float ev = tanh5(o);
        int q = __float2int_rn(ev * QSCALE);
        g_eq[base + n] = (short)q;
        // stats on the DECODED value so mean/std match what out_kernel reads
        float evd = (float)q * QINV;
        ls += evd;
        lq = fmaf(evd, evd, lq);
    }

    __shared__ float reds[256];
    __shared__ float redq[256];
    __shared__ bool amLast;
    reds[tid] = ls; redq[tid] = lq; __syncthreads();
    for (int s = 128; s; s >>= 1) {
        if (tid < s) { reds[tid] += reds[tid + s]; redq[tid] += redq[tid + s]; }
        __syncthreads();
    }
    if (tid == 0) {
        int pid = blockIdx.y * gridDim.x + blockIdx.x;
        g_psum[pid] = reds[0];
        g_psumsq[pid] = redq[0];
        __threadfence();                       // release partials
        unsigned int t = atomicAdd(&g_done, 1u);
        amLast = (t == 2048u - 1u);
    }
    __syncthreads();

    // Last block: deterministic fixed-order fp64 stats reduce + PWL generator.
    if (amLast) {
        __threadfence();                       // acquire all partials
        __shared__ double sds[256];
        double s = 0.0, q = 0.0;
#pragma unroll
        for (int i = 0; i < 8; i++) {
            int idx = tid + i * 256;
            s += (double)g_psum[idx];
            q += (double)g_psumsq[idx];
        }
        sds[tid] = s; __syncthreads();
        for (int k = 128; k; k >>= 1) {
            if (tid < k) sds[tid] += sds[tid + k];
            __syncthreads();
        }
        double stot = sds[0]; __syncthreads();
        sds[tid] = q; __syncthreads();
        for (int k = 128; k; k >>= 1) {
            if (tid < k) sds[tid] += sds[tid + k];
            __syncthreads();
        }
        double qtot = sds[0];
        if (tid == 0) {
            double CN = (double)C_CH * (double)N_PTS;
            double mean = stot / CN;
            double var = (qtot - stot * stot / CN) / (CN - 1.0);
            double invstd = 1.0 / sqrt(var);
            g_eA = (float)(0.1 * invstd * (double)QINV);  // decode folded in
            g_eB = (float)(-0.1 * mean * invstd);
            g_done = 0u;                       // reset for next graph replay
        }
        if (tid < C_CH) {
            int mn = g_min_q[tid];             // pass_x completed (stream order)
            int mx = g_max_q[tid];
            g_minv[tid] = (float)mn;
            g_scale[tid] = 1.0f / (float)(mx - mn);
        }
        // PWL generator (formerly its own kernel launch). Block-uniform path.
        gen_pwl_inline(tid, zf, Wf1, bf1, Wf2, bf2, dirs_raw,
                       (unsigned int*)&sds[0]);
        __threadfence();
    }
}

// ---------------- K3: transpose + direct-index PWL + noise (double-buffered) ----------------
__global__ void __launch_bounds__(256) out_kernel(float* __restrict__ out) {
    __shared__ float sx[2][32][33];
    __shared__ float se[2][32][33];
    __shared__ float ssl[32][NSEG + 1];
    __shared__ float ssb[32][NSEG + 1];
    __shared__ float smn[32];
    __shared__ float ssc[32];

    const int tx = threadIdx.x, ty = threadIdx.y;
    const int tid = ty * 32 + tx;
    const int nb = blockIdx.x * 128;
    const int c0 = blockIdx.y * 32;

    for (int idx = tid; idx < 32 * NSEG; idx += 256) {
        int cl = idx / NSEG, k = idx % NSEG;
        ssl[cl][k] = g_slope[(c0 + cl) * NSEG + k];
        ssb[cl][k] = g_icept[(c0 + cl) * NSEG + k];
    }
    if (tid < 32) {
        smn[tid] = g_minv[c0 + tid];
        ssc[tid] = g_scale[c0 + tid];
    }
    // Re-arm min/max for the NEXT graph replay (pass_e finalize of THIS run
    // already consumed them; stream order makes this safe).
    if (blockIdx.x == 0 && tid >= 32 && tid < 64) {
        int cc = c0 + tid - 32;
        g_min_q[cc] = 0x7FFFFFFF;
        g_max_q[cc] = (int)0x80000000;
    }
    const float eA = g_eA, eB = g_eB;

    // Preload tile 0 (decode int16 -> float at load time)
    float rx[4], re[4];
#pragma unroll
    for (int r = 0; r < 4; r++) {
        int cl = ty + r * 8;
        size_t off = (size_t)(c0 + cl) * N_PTS + nb + tx;
        rx[r] = (float)g_xq[off];
        re[r] = (float)g_eq[off];
    }
#pragma unroll
    for (int r = 0; r < 4; r++) {
        int cl = ty + r * 8;
        sx[0][cl][tx] = rx[r];
        se[0][cl][tx] = re[r];
    }
    __syncthreads();

    const float mn = smn[tx], sc = ssc[tx];

#pragma unroll
    for (int t = 0; t < 4; t++) {
        const int cur = t & 1;
        if (t < 3) {
            const int n1 = nb + (t + 1) * 32;
#pragma unroll
            for (int r = 0; r < 4; r++) {
                int cl = ty + r * 8;
                size_t off = (size_t)(c0 + cl) * N_PTS + n1 + tx;
                rx[r] = (float)g_xq[off];
                re[r] = (float)g_eq[off];
            }
        }
        const int n0 = nb + t * 32;
#pragma unroll
        for (int r = 0; r < 4; r++) {
            int nn = ty + r * 8;
            float xv = (sx[cur][tx][nn] - mn) * sc;
            int j = min(max(__float2int_rd(xv * 19.0f), 0), NSEG - 1);
            float y = fmaf(xv, ssl[tx][j], ssb[tx][j]);
            out[(size_t)(n0 + nn) * C_CH + c0 + tx] = fmaf(se[cur][tx][nn], eA, y + eB);
        }
        if (t < 3) {
            __syncthreads();
            const int nxt = (t + 1) & 1;
#pragma unroll
            for (int r = 0; r < 4; r++) {
                int cl = ty + r * 8;
                sx[nxt][cl][tx] = rx[r];
                se[nxt][cl][tx] = re[r];
            }
            __syncthreads();
        }
    }
}

// ---------------- launch ----------------
extern "C" void kernel_launch(void* const* d_in, const int* in_sizes, int n_in,
                              void* d_out, int out_size) {
    const float* zf  = (const float*)d_in[0];
    const float* zx  = (const float*)d_in[1];
    const float* ze  = (const float*)d_in[2];
    const float* Wx1 = (const float*)d_in[3];
    const float* bx1 = (const float*)d_in[4];
    const float* Wx2 = (const float*)d_in[5];
    const float* bx2 = (const float*)d_in[6];
    const float* We1 = (const float*)d_in[7];
    const float* be1 = (const float*)d_in[8];
    const float* We2 = (const float*)d_in[9];
    const float* be2 = (const float*)d_in[10];
    const float* Wf1 = (const float*)d_in[11];
    const float* bf1 = (const float*)d_in[12];
    const float* Wf2 = (const float*)d_in[13];
    const float* bf2 = (const float*)d_in[14];
    const void*  dirs = d_in[15];
    float* out = (float*)d_out;

    pass_x_kernel<<<dim3(16, 128), 256>>>(zx, Wx1, bx1, Wx2, bx2);
    pass_e_kernel<<<dim3(16, 128), 256>>>(ze, We1, be1, We2, be2,
                                          zf, Wf1, bf1, Wf2, bf2, dirs);
    out_kernel<<<dim3(N_PTS / 128, C_CH / 32), dim3(32, 8)>>>(out);
}

// round 17
// speedup vs baseline: 1.1031x; 1.1031x over previous
#include <cuda_runtime.h>
#include <cuda_bf16.h>
#include <math.h>
#include <stdint.h>

#define C_CH   128
#define N_PTS  32768
#define K_PWL  20
#define LATENT 8
#define HID    8
#define NSEG   (K_PWL - 1)

// ---------------- scratch (static device memory; no allocations) ----------------
// x/e stored as int16 fixed-point: q = round(v * 32767), |v| <= 1 (tanh output).
__device__ short g_xq[(size_t)C_CH * N_PTS];
__device__ short g_eq[(size_t)C_CH * N_PTS];
__device__ float g_slope[C_CH * NSEG];
__device__ float g_icept[C_CH * NSEG];
__device__ int   g_min_q[C_CH];
__device__ int   g_max_q[C_CH];
__device__ float g_minv[C_CH];
__device__ float g_scale[C_CH];
__device__ float g_psum[2048];
__device__ float g_psumsq[2048];
__device__ float g_eA;   // 0.1 * invstd * (1/32767)
__device__ float g_eB;   // -0.1 * mean * invstd
__device__ unsigned int g_done;  // zero-init; self-resets each run

#define QSCALE 32767.0f
#define QINV   (1.0f / 32767.0f)

// xp = linspace(0,1,20) in f32
#define XPV(k) ((float)((double)(k) / 19.0))
__constant__ float c_xp[K_PWL] = {
    XPV(0), XPV(1), XPV(2), XPV(3), XPV(4), XPV(5), XPV(6), XPV(7), XPV(8), XPV(9),
    XPV(10), XPV(11), XPV(12), XPV(13), XPV(14), XPV(15), XPV(16), XPV(17), XPV(18), XPV(19)
};

// ---------------- helpers ----------------
// Clamped fast tanh (gen kernel only; off the hot loop).
__device__ __forceinline__ float tanh_fast(float x) {
    x = fminf(fmaxf(x, -30.0f), 30.0f);
    float t = __expf(2.0f * x);
    return __fdividef(t - 1.0f, t + 1.0f);
}

// Lean 5-instruction tanh (validated rounds 13-16).
__device__ __forceinline__ float tanh5(float x) {
    float t;
    asm("ex2.approx.f32 %0, %1;" : "=f"(t) : "f"(x * 2.8853900817779268f));
    float r;
    asm("rcp.approx.f32 %0, %1;" : "=f"(r) : "f"(t + 1.0f));
    return fmaf(t, r, -r);
}

// ---------------- K1: PWL generator (tiny, standalone — folding it into a pass
// kernel inflates that kernel's register allocation; proven twice, R9/R16) ----------------
__global__ void gen_pwl_kernel(const float* __restrict__ zf,
                               const float* __restrict__ Wf1, const float* __restrict__ bf1,
                               const float* __restrict__ Wf2, const float* __restrict__ bf2,
                               const void* __restrict__ dirs_raw) {
    int c = threadIdx.x;  // 128 threads, one per channel
    __shared__ unsigned int flags;
    if (c == 0) { flags = 0u; g_done = 0u; }
    __syncthreads();
    {
        unsigned char v = ((const unsigned char*)dirs_raw)[c];
        unsigned int f = 0u;
        if ((c & 3) != 0 && v != 0) f |= 1u;
        if (v > 1) f |= 2u;
        if (f) atomicOr(&flags, f);
    }
    __syncthreads();
    // mode: 0 = int32, 1 = uint8/bool, 2 = float32
    const int mode = (!(flags & 1u)) ? 0 : ((!(flags & 2u)) ? 1 : 2);

    float z[LATENT];
#pragma unroll
    for (int i = 0; i < LATENT; i++) z[i] = zf[c * LATENT + i];

    float h[HID];
#pragma unroll
    for (int j = 0; j < HID; j++) h[j] = bf1[j];
#pragma unroll
    for (int i = 0; i < LATENT; i++)
#pragma unroll
        for (int j = 0; j < HID; j++) h[j] = fmaf(z[i], Wf1[i * HID + j], h[j]);
#pragma unroll
    for (int j = 0; j < HID; j++) h[j] = tanh_fast(h[j]);

    float pts[K_PWL];
#pragma unroll
    for (int k = 0; k < K_PWL; k++) {
        float s = bf2[k];
#pragma unroll
        for (int j = 0; j < HID; j++) s = fmaf(h[j], Wf2[j * K_PWL + k], s);
        pts[k] = tanh_fast(s);
    }
    // insertion sort ascending
    for (int a = 1; a < K_PWL; a++) {
        float v = pts[a];
        int b = a - 1;
        while (b >= 0 && pts[b] > v) { pts[b + 1] = pts[b]; b--; }
        pts[b + 1] = v;
    }
    bool dir;
    if (mode == 0)      dir = ((const int*)dirs_raw)[c] != 0;
    else if (mode == 1) dir = ((const unsigned char*)dirs_raw)[c] != 0;
    else                dir = ((const float*)dirs_raw)[c] > 0.5f;

    // Per-segment slope/intercept: y(xv) = sl*xv + ic on [xp[k], xp[k+1]]
    for (int k = 0; k < NSEG; k++) {
        float y0 = dir ? pts[k]     : pts[K_PWL - 1 - k];
        float y1 = dir ? pts[k + 1] : pts[K_PWL - 2 - k];
        float sl = (y1 - y0) / (c_xp[k + 1] - c_xp[k] + 1e-7f);
        g_slope[c * NSEG + k] = sl;
        g_icept[c * NSEG + k] = fmaf(-c_xp[k], sl, y0);
    }

    g_min_q[c] = 0x7FFFFFFF;
    g_max_q[c] = (int)0x80000000;
}

// ---------------- K2: x MLP + per-channel min/max (int16 scratch) ----------------
__global__ void __launch_bounds__(256) pass_x_kernel(
    const float* __restrict__ zx,
    const float* __restrict__ W1, const float* __restrict__ b1,
    const float* __restrict__ W2, const float* __restrict__ b2) {
    float W1r[64];
#pragma unroll
    for (int i = 0; i < 64; i++) W1r[i] = __ldg(W1 + i);
    float b1r[HID], W2r[HID];
#pragma unroll
    for (int j = 0; j < HID; j++) { b1r[j] = __ldg(b1 + j); W2r[j] = __ldg(W2 + j); }
    float b2r = __ldg(b2);

    const int c = blockIdx.y;
    const int tid = threadIdx.x;
    const size_t base = (size_t)c * N_PTS;
    const int n0 = blockIdx.x * 2048;

    int lmin = 0x7FFFFFFF, lmax = (int)0x80000000;
#pragma unroll
    for (int k = 0; k < 8; k++) {
        int n = n0 + k * 256 + tid;
        const float4* p = reinterpret_cast<const float4*>(zx + (base + n) * LATENT);
        float4 a = p[0], bq = p[1];
        float z[8] = {a.x, a.y, a.z, a.w, bq.x, bq.y, bq.z, bq.w};
        float h[HID];
#pragma unroll
        for (int j = 0; j < HID; j++) h[j] = b1r[j];
#pragma unroll
        for (int i = 0; i < LATENT; i++)
#pragma unroll
            for (int j = 0; j < HID; j++) h[j] = fmaf(z[i], W1r[i * HID + j], h[j]);
        float o = b2r;
#pragma unroll
        for (int j = 0; j < HID; j++) o = fmaf(tanh5(h[j]), W2r[j], o);
        float xv = tanh5(o);
        int q = __float2int_rn(xv * QSCALE);
        g_xq[base + n] = (short)q;
        lmin = min(lmin, q);
        lmax = max(lmax, q);
    }

    __shared__ int red1[256];
    __shared__ int red2[256];
    red1[tid] = lmin; red2[tid] = lmax; __syncthreads();
    for (int s = 128; s; s >>= 1) {
        if (tid < s) {
            red1[tid] = min(red1[tid], red1[tid + s]);
            red2[tid] = max(red2[tid], red2[tid + s]);
        }
        __syncthreads();
    }
    if (tid == 0) {
        atomicMin(&g_min_q[c], red1[0]);
        atomicMax(&g_max_q[c], red2[0]);
    }
}

// ---------------- K3: e MLP + global sum/sumsq partials + last-block finalize ----------------
__global__ void __launch_bounds__(256) pass_e_kernel(
    const float* __restrict__ ze,
    const float* __restrict__ W1, const float* __restrict__ b1,
    const float* __restrict__ W2, const float* __restrict__ b2) {
    float W1r[64];
#pragma unroll
    for (int i = 0; i < 64; i++) W1r[i] = __ldg(W1 + i);
    float b1r[HID], W2r[HID];
#pragma unroll
    for (int j = 0; j < HID; j++) { b1r[j] = __ldg(b1 + j); W2r[j] = __ldg(W2 + j); }
    float b2r = __ldg(b2);

    const int c = blockIdx.y;
    const int tid = threadIdx.x;
    const size_t base = (size_t)c * N_PTS;
    const int n0 = blockIdx.x * 2048;

    float ls = 0.0f, lq = 0.0f;
#pragma unroll
    for (int k = 0; k < 8; k++) {
        int n = n0 + k * 256 + tid;
        const float4* p = reinterpret_cast<const float4*>(ze + (base + n) * LATENT);
        float4 a = p[0], bq = p[1];
        float z[8] = {a.x, a.y, a.z, a.w, bq.x, bq.y, bq.z, bq.w};
        float h[HID];
#pragma unroll
        for (int j = 0; j < HID; j++) h[j] = b1r[j];
#pragma unroll
        for (int i = 0; i < LATENT; i++)
#pragma unroll
            for (int j = 0; j < HID; j++) h[j] = fmaf(z[i], W1r[i * HID + j], h[j]);
        float o = b2r;
#pragma unroll
        for (int j = 0; j < HID; j++) o = fmaf(tanh5(h[j]), W2r[j], o);
        float ev = tanh5(o);
        int q = __float2int_rn(ev * QSCALE);
        g_eq[base + n] = (short)q;
        // stats on the DECODED value so mean/std match what out_kernel reads
        float evd = (float)q * QINV;
        ls += evd;
        lq = fmaf(evd, evd, lq);
    }

    __shared__ float reds[256];
    __shared__ float redq[256];
    __shared__ bool amLast;
    reds[tid] = ls; redq[tid] = lq; __syncthreads();
    for (int s = 128; s; s >>= 1) {
        if (tid < s) { reds[tid] += reds[tid + s]; redq[tid] += redq[tid + s]; }
        __syncthreads();
    }
    if (tid == 0) {
        int pid = blockIdx.y * gridDim.x + blockIdx.x;
        g_psum[pid] = reds[0];
        g_psumsq[pid] = redq[0];
        __threadfence();                       // release partials
        unsigned int t = atomicAdd(&g_done, 1u);
        amLast = (t == 2048u - 1u);
    }
    __syncthreads();

    // Last block performs the deterministic fixed-order fp64 reduce.
    if (amLast) {
        __threadfence();                       // acquire all partials
        __shared__ double sds[256];
        double s = 0.0, q = 0.0;
#pragma unroll
        for (int i = 0; i < 8; i++) {
            int idx = tid + i * 256;
            s += (double)g_psum[idx];
            q += (double)g_psumsq[idx];
        }
        sds[tid] = s; __syncthreads();
        for (int k = 128; k; k >>= 1) {
            if (tid < k) sds[tid] += sds[tid + k];
            __syncthreads();
        }
        double stot = sds[0]; __syncthreads();
        sds[tid] = q; __syncthreads();
        for (int k = 128; k; k >>= 1) {
            if (tid < k) sds[tid] += sds[tid + k];
            __syncthreads();
        }
        double qtot = sds[0];
        if (tid == 0) {
            double CN = (double)C_CH * (double)N_PTS;
            double mean = stot / CN;
            double var = (qtot - stot * stot / CN) / (CN - 1.0);
            double invstd = 1.0 / sqrt(var);
            g_eA = (float)(0.1 * invstd * (double)QINV);  // decode folded in
            g_eB = (float)(-0.1 * mean * invstd);
            g_done = 0u;                       // reset for next graph replay
        }
        if (tid < C_CH) {
            int mn = g_min_q[tid];             // pass_x completed (stream order)
            int mx = g_max_q[tid];
            g_minv[tid] = (float)mn;
            g_scale[tid] = 1.0f / (float)(mx - mn);
        }
        __threadfence();
    }
}

// ---------------- K4: transpose + direct-index PWL + noise (vectorized, swizzled) ----------------
// Tile: 32 channels x 128 n. Load: short4 (8B) per thread -> float4 -> STS.128
// into XOR-swizzled float4 tile (conflict-free). Compute: LDS.128 (4 n/lane),
// 4 coalesced STG.32. Single sync phase.
__global__ void __launch_bounds__(256) out_kernel(float* __restrict__ out) {
    __shared__ float4 sx4[32][32];      // [channel][swizzled n-chunk]
    __shared__ float4 se4[32][32];
    __shared__ float ssl[32][21];       // 21: conflict-free column reads
    __shared__ float ssb[32][21];
    __shared__ float smn[32];
    __shared__ float ssc[32];

    const int tx = threadIdx.x, ty = threadIdx.y;
    const int tid = ty * 32 + tx;
    const int nb = blockIdx.x * 128;
    const int c0 = blockIdx.y * 32;

    for (int idx = tid; idx < 32 * NSEG; idx += 256) {
        int cl = idx / NSEG, k = idx % NSEG;
        ssl[cl][k] = g_slope[(c0 + cl) * NSEG + k];
        ssb[cl][k] = g_icept[(c0 + cl) * NSEG + k];
    }
    if (tid < 32) {
        smn[tid] = g_minv[c0 + tid];
        ssc[tid] = g_scale[c0 + tid];
    }
    const float eA = g_eA, eB = g_eB;

    // Load phase: thread (tx,ty) loads rows cl=ty+8r, shorts [4tx..4tx+3].
#pragma unroll
    for (int r = 0; r < 4; r++) {
        int cl = ty + r * 8;
        size_t offs = (size_t)(c0 + cl) * N_PTS + nb + 4 * tx;   // 8B aligned
        short4 qx = *reinterpret_cast<const short4*>(g_xq + offs);
        short4 qe = *reinterpret_cast<const short4*>(g_eq + offs);
        int ch = (tx ^ cl) & 31;
        sx4[cl][ch] = make_float4((float)qx.x, (float)qx.y, (float)qx.z, (float)qx.w);
        se4[cl][ch] = make_float4((float)qe.x, (float)qe.y, (float)qe.z, (float)qe.w);
    }
    __syncthreads();

    // Compute phase: thread handles channel c = tx, n-chunks k = ty + 8r.
    const float mn = smn[tx], sc = ssc[tx];
#pragma unroll
    for (int r = 0; r < 4; r++) {
        int k = ty + r * 8;
        int ch = (k ^ tx) & 31;
        float4 vx = sx4[tx][ch];
        float4 ve = se4[tx][ch];
        const int nbase = nb + 4 * k;
        float xs[4] = {vx.x, vx.y, vx.z, vx.w};
        float es[4] = {ve.x, ve.y, ve.z, ve.w};
#pragma unroll
        for (int i = 0; i < 4; i++) {
            float xv = (xs[i] - mn) * sc;
            int j = min(max(__float2int_rd(xv * 19.0f), 0), NSEG - 1);
            float y = fmaf(xv, ssl[tx][j], ssb[tx][j]);
            out[(size_t)(nbase + i) * C_CH + c0 + tx] = fmaf(es[i], eA, y + eB);
        }
    }
}

// ---------------- launch ----------------
extern "C" void kernel_launch(void* const* d_in, const int* in_sizes, int n_in,
                              void* d_out, int out_size) {
    const float* zf  = (const float*)d_in[0];
    const float* zx  = (const float*)d_in[1];
    const float* ze  = (const float*)d_in[2];
    const float* Wx1 = (const float*)d_in[3];
    const float* bx1 = (const float*)d_in[4];
    const float* Wx2 = (const float*)d_in[5];
    const float* bx2 = (const float*)d_in[6];
    const float* We1 = (const float*)d_in[7];
    const float* be1 = (const float*)d_in[8];
    const float* We2 = (const float*)d_in[9];
    const float* be2 = (const float*)d_in[10];
    const float* Wf1 = (const float*)d_in[11];
    const float* bf1 = (const float*)d_in[12];
    const float* Wf2 = (const float*)d_in[13];
    const float* bf2 = (const float*)d_in[14];
    const void*  dirs = d_in[15];
    float* out = (float*)d_out;

    gen_pwl_kernel<<<1, 128>>>(zf, Wf1, bf1, Wf2, bf2, dirs);
    pass_x_kernel<<<dim3(16, 128), 256>>>(zx, Wx1, bx1, Wx2, bx2);
    pass_e_kernel<<<dim3(16, 128), 256>>>(ze, We1, be1, We2, be2);
    out_kernel<<<dim3(N_PTS / 128, C_CH / 32), dim3(32, 8)>>>(out);
}